// round 15
// baseline (speedup 1.0000x reference)
#include <cuda_runtime.h>
#include <cuda_fp16.h>
#include <cstdint>

#define NB 65536
#define NT 100

// ---- activations ----
__device__ __forceinline__ float tanhfast(float x){
  float y; asm("tanh.approx.f32 %0, %1;" : "=f"(y) : "f"(x)); return y;
}
__device__ __forceinline__ uint32_t tanh2fast(uint32_t x){
  uint32_t y; asm("tanh.approx.f16x2 %0, %1;" : "=r"(y) : "r"(x)); return y;
}

// per-lane partial dots + 3-shfl butterfly transpose-reduce over the 4-lane group
__device__ __forceinline__ float gate_reduce(float4 x,
    const float4 &w0, const float4 &w1, const float4 &w2, const float4 &w3,
    int dblk, float bsum)
{
  float p0 = x.x*w0.x + x.y*w0.y + x.z*w0.z + x.w*w0.w;
  float p1 = x.x*w1.x + x.y*w1.y + x.z*w1.z + x.w*w1.w;
  float p2 = x.x*w2.x + x.y*w2.y + x.z*w2.z + x.w*w2.w;
  float p3 = x.x*w3.x + x.y*w3.y + x.z*w3.z + x.w*w3.w;
  float s01 = (dblk & 1) ? p0 : p1;
  float r01 = __shfl_xor_sync(0xffffffffu, s01, 1);
  float a   = ((dblk & 1) ? p1 : p0) + r01;
  float s23 = (dblk & 1) ? p2 : p3;
  float r23 = __shfl_xor_sync(0xffffffffu, s23, 1);
  float bb  = ((dblk & 1) ? p3 : p2) + r23;
  float snd = (dblk & 2) ? a : bb;
  float rcv = __shfl_xor_sync(0xffffffffu, snd, 2);
  return ((dblk & 2) ? bb : a) + rcv + bsum;
}

__device__ __forceinline__ void store_gate_h2(unsigned* sp, float gv, int dblk){
  float ghi = __shfl_xor_sync(0xffffffffu, gv, 1);
  if (!(dblk & 1)){
    __half2 hh = __floats2half2_rn(gv, ghi);
    *sp = *(const unsigned*)&hh;
  }
}

// 52 MB fp16 gate scratch: per (t,b) one uint2 = {half2(si, sf), half2(g, so)}
// where si/sf/so are PRE-SCALED by 0.5 (sigmoid-via-tanh folding).
__device__ uint2 g_scratch16[(size_t)NB * NT];

// ============================================================================
// Kernel A: gate precompute -> fp16 scratch. X read with .cs (evict-first)
// so the gate lines stay L2-resident for kernel B. Gates 0,1,3 pre-scaled 0.5.
// ============================================================================
__global__ __launch_bounds__(512)
void gates_kernel(const float* __restrict__ X,   const float* __restrict__ Wih,
                  const float* __restrict__ bih, const float* __restrict__ bhh)
{
  const int lane = threadIdx.x & 31;
  const int wg   = (blockIdx.x * 512 + threadIdx.x) >> 5;
  const int b_i  = lane >> 3;
  const int t_i  = (lane >> 2) & 1;
  const int dblk = lane & 3;

  float4 w0 = *(const float4*)(Wih +  0 + dblk*4);
  float4 w1 = *(const float4*)(Wih + 16 + dblk*4);
  const float4 w2 = *(const float4*)(Wih + 32 + dblk*4);
  float4 w3 = *(const float4*)(Wih + 48 + dblk*4);
  // fold 0.5 sigmoid pre-scale into gate 0,1,3 weights
  w0.x *= 0.5f; w0.y *= 0.5f; w0.z *= 0.5f; w0.w *= 0.5f;
  w1.x *= 0.5f; w1.y *= 0.5f; w1.z *= 0.5f; w1.w *= 0.5f;
  w3.x *= 0.5f; w3.y *= 0.5f; w3.z *= 0.5f; w3.w *= 0.5f;
  const float bscale = (dblk == 2) ? 1.f : 0.5f;
  const float bsum = (bih[dblk] + bhh[dblk]) * bscale;

  #pragma unroll 1
  for (int rep = 0; rep < 2; rep++){
    const int b = (wg + rep*8192)*4 + b_i;
    const float4* xp = (const float4*)X + ((size_t)b*NT + t_i)*4 + dblk;
    unsigned* sp = (unsigned*)g_scratch16 + ((size_t)t_i*NB + b)*2 + (dblk >> 1);

    #pragma unroll 1
    for (int t0 = 0; t0 < 96; t0 += 8){
      float4 xv[4];
      xv[0] = __ldcs(xp);
      xv[1] = __ldcs(xp + 8);
      xv[2] = __ldcs(xp + 16);
      xv[3] = __ldcs(xp + 24);
      xp += 32;
      #pragma unroll
      for (int q = 0; q < 4; q++){
        float gv = gate_reduce(xv[q], w0, w1, w2, w3, dblk, bsum);
        store_gate_h2(sp + (size_t)(2*q)*NB*2, gv, dblk);
      }
      sp += (size_t)8*NB*2;
    }
    {
      float4 xa = __ldcs(xp), xb = __ldcs(xp + 8);
      float ga = gate_reduce(xa, w0, w1, w2, w3, dblk, bsum);
      float gb = gate_reduce(xb, w0, w1, w2, w3, dblk, bsum);
      store_gate_h2(sp, ga, dblk);
      store_gate_h2(sp + (size_t)2*NB*2, gb, dblk);
    }
  }
}

// ============================================================================
// Kernel B: LSTM scan (triple-buffered prefetch, f16x2 tanh activations)
// + HMMA (m16n8k16) for both dense layers.
// ============================================================================
#define SMEM_A 0
#define SMEM_B 30720
#define SMEM_TOT 46080
#define PITCH 240

static __device__ __forceinline__ uint32_t smem_u32(const void* p){
  uint32_t a;
  asm("{ .reg .u64 t; cvta.to.shared.u64 t, %1; cvt.u32.u64 %0, t; }" : "=r"(a) : "l"(p));
  return a;
}
__device__ __forceinline__ void ldsm_x4(uint32_t* r, uint32_t addr){
  asm volatile("ldmatrix.sync.aligned.m8n8.x4.shared.b16 {%0,%1,%2,%3}, [%4];"
    : "=r"(r[0]),"=r"(r[1]),"=r"(r[2]),"=r"(r[3]) : "r"(addr));
}
__device__ __forceinline__ void ldsm_x2(uint32_t* r, uint32_t addr){
  asm volatile("ldmatrix.sync.aligned.m8n8.x2.shared.b16 {%0,%1}, [%2];"
    : "=r"(r[0]),"=r"(r[1]) : "r"(addr));
}
__device__ __forceinline__ void mma16816(float* c, const uint32_t* a, const uint32_t* b){
  asm volatile("mma.sync.aligned.m16n8k16.row.col.f32.f16.f16.f32 "
    "{%0,%1,%2,%3}, {%4,%5,%6,%7}, {%8,%9}, {%0,%1,%2,%3};"
    : "+f"(c[0]),"+f"(c[1]),"+f"(c[2]),"+f"(c[3])
    : "r"(a[0]),"r"(a[1]),"r"(a[2]),"r"(a[3]), "r"(b[0]),"r"(b[1]));
}

__device__ __forceinline__ void load_group8(uint2 (&buf)[8], const uint2* gbase, int g){
  const uint2* p = gbase + (size_t)(g*8)*NB;
  #pragma unroll
  for (int i = 0; i < 8; i++) buf[i] = __ldcs(p + (size_t)i*NB);
}
__device__ __forceinline__ void load_group4(uint2 (&buf)[8], const uint2* gbase, int g){
  const uint2* p = gbase + (size_t)(g*8)*NB;
  #pragma unroll
  for (int i = 0; i < 4; i++) buf[i] = __ldcs(p + (size_t)i*NB);
}

template<int CNT>
__device__ __forceinline__ void consume_group(const uint2 (&buf)[8], float &h, float &c,
    __half2 whh01h, __half2 whh23h, float (&hv)[8])
{
  #pragma unroll
  for (int s = 0; s < CNT; s++){
    uint2 u = buf[s];
    __half2 h2  = __float2half2_rn(h);
    __half2 p01 = __hfma2(h2, whh01h, *(const __half2*)&u.x);  // (0.5 xi, 0.5 xf)
    __half2 p23 = __hfma2(h2, whh23h, *(const __half2*)&u.y);  // (xg, 0.5 xo)
    uint32_t t01u = tanh2fast(*(const uint32_t*)&p01);
    uint32_t t23u = tanh2fast(*(const uint32_t*)&p23);
    float2 t01 = __half22float2(*(const __half2*)&t01u);
    float2 t23 = __half22float2(*(const __half2*)&t23u);
    float gi = 0.5f + 0.5f*t01.x;
    float gf = 0.5f + 0.5f*t01.y;
    float gg = t23.x;
    float go = 0.5f + 0.5f*t23.y;
    c = gf*c + gi*gg;
    h = go * tanhfast(c);
    hv[s] = fmaxf(h, 0.f);
  }
}

__device__ __forceinline__ void flush_group8(char* arow, int g, const float (&hv)[8]){
  __half2 p0 = __floats2half2_rn(hv[0], hv[1]);
  __half2 p1 = __floats2half2_rn(hv[2], hv[3]);
  __half2 p2 = __floats2half2_rn(hv[4], hv[5]);
  __half2 p3 = __floats2half2_rn(hv[6], hv[7]);
  *(uint4*)(arow + g*16) =
    make_uint4(*(uint32_t*)&p0, *(uint32_t*)&p1, *(uint32_t*)&p2, *(uint32_t*)&p3);
}

__global__ __launch_bounds__(128, 4)
void scan_kernel(const float* __restrict__ Whh, const float* __restrict__ W1,
                 const float* __restrict__ b1,  const float* __restrict__ W2,
                 const float* __restrict__ b2,  const float* __restrict__ W3,
                 const float* __restrict__ b3,  float* __restrict__ out)
{
  extern __shared__ char smem[];
  const int tid  = threadIdx.x;
  const int wid  = tid >> 5;
  const int lane = tid & 31;
  const int b    = blockIdx.x * 128 + tid;
  const uint32_t sbase = smem_u32(smem);

  const uint2* gbase = g_scratch16 + b;

  // prologue: issue groups 0,1,2 (24 loads in flight) before staging
  uint2 bf0[8], bf1[8], bf2[8];
  load_group8(bf0, gbase, 0);
  load_group8(bf1, gbase, 1);
  load_group8(bf2, gbase, 2);

  // zero A+B regions (provides K zero-padding cols 100..111)
  {
    uint4 z4 = make_uint4(0,0,0,0);
    uint4* zp = (uint4*)smem;
    for (int i = tid; i < SMEM_TOT/16; i += 128) zp[i] = z4;
  }
  __syncthreads();

  // stage W1 -> B as [n=j][k=t] fp16
  {
    __half* sB = (__half*)(smem + SMEM_B);
    for (int i = tid; i < 6400; i += 128){
      int j = i / 100, t = i % 100;
      sB[j*120 + t] = __float2half(W1[i]);
    }
  }

  // ---- scan: 12 groups of 8 + tail of 4; distance-16..24 prefetch ----
  const __half2 whh01h = __floats2half2_rn(0.5f*Whh[0], 0.5f*Whh[1]);
  const __half2 whh23h = __floats2half2_rn(Whh[2],      0.5f*Whh[3]);
  char* arow = smem + SMEM_A + tid*PITCH;
  float h = 0.f, c = 0.f;
  float hv[8];

  #pragma unroll 1
  for (int q = 0; q < 4; q++){
    const int g = q*3;
    consume_group<8>(bf0, h, c, whh01h, whh23h, hv);
    if (g + 3 < 12)       load_group8(bf0, gbase, g + 3);
    else if (g + 3 == 12) load_group4(bf0, gbase, 12);
    flush_group8(arow, g, hv);

    consume_group<8>(bf1, h, c, whh01h, whh23h, hv);
    if (g + 4 < 12) load_group8(bf1, gbase, g + 4);
    flush_group8(arow, g + 1, hv);

    consume_group<8>(bf2, h, c, whh01h, whh23h, hv);
    if (g + 5 < 12) load_group8(bf2, gbase, g + 5);
    flush_group8(arow, g + 2, hv);
  }
  // tail: steps 96..99 in bf0 (loaded at g=9)
  consume_group<4>(bf0, h, c, whh01h, whh23h, hv);
  {
    __half2 p0 = __floats2half2_rn(hv[0], hv[1]);
    __half2 p1 = __floats2half2_rn(hv[2], hv[3]);
    *(uint4*)(arow + 192) = make_uint4(*(uint32_t*)&p0, *(uint32_t*)&p1, 0u, 0u);
  }
  __syncthreads();   // all 128 A rows + W1 staged before MMA

  // ldmatrix per-lane base addresses
  const uint32_t a_lm = sbase + SMEM_A
      + (uint32_t)(wid*32 + (lane & 7) + ((lane >> 3) & 1)*8)*PITCH
      + (uint32_t)((lane >> 4) & 1)*16;
  const uint32_t b_lm = sbase + SMEM_B
      + (uint32_t)(lane & 7)*PITCH + (uint32_t)((lane >> 3) & 1)*16;

  // ---- MMA-1: y1[128,64] = hr[128,112] @ W1^T (7 k-steps) ----
  float c1[2][8][4];
  #pragma unroll
  for (int mi = 0; mi < 2; mi++)
    #pragma unroll
    for (int ni = 0; ni < 8; ni++)
      #pragma unroll
      for (int qq = 0; qq < 4; qq++) c1[mi][ni][qq] = 0.f;

  #pragma unroll
  for (int k = 0; k < 7; k++){
    uint32_t bfm[8][2];
    #pragma unroll
    for (int ni = 0; ni < 8; ni++) ldsm_x2(bfm[ni], b_lm + ni*(8*PITCH) + k*32);
    #pragma unroll
    for (int mi = 0; mi < 2; mi++){
      uint32_t af[4];
      ldsm_x4(af, a_lm + mi*(16*PITCH) + k*32);
      #pragma unroll
      for (int ni = 0; ni < 8; ni++) mma16816(c1[mi][ni], af, bfm[ni]);
    }
  }
  __syncthreads();   // everyone done reading A (hr) and B (W1)

  // ---- relu(y1+b1) -> A2 (cols 0..63 of A region); stage W2 -> B ----
  {
    __half* sB = (__half*)(smem + SMEM_B);
    for (int i = tid; i < 4096; i += 128){
      int ko = i >> 6, j = i & 63;
      sB[ko*120 + j] = __float2half(W2[i]);
    }
  }
  {
    const int col = (lane & 3)*2;
    const int r0  = wid*32 + (lane >> 2);
    #pragma unroll
    for (int ni = 0; ni < 8; ni++){
      int cc = ni*8 + col;
      float b1a = __ldg(b1 + cc), b1b = __ldg(b1 + cc + 1);
      #pragma unroll
      for (int mi = 0; mi < 2; mi++){
        float v0 = fmaxf(c1[mi][ni][0] + b1a, 0.f);
        float v1 = fmaxf(c1[mi][ni][1] + b1b, 0.f);
        float v2 = fmaxf(c1[mi][ni][2] + b1a, 0.f);
        float v3 = fmaxf(c1[mi][ni][3] + b1b, 0.f);
        __half2 h01 = __floats2half2_rn(v0, v1);
        __half2 h23 = __floats2half2_rn(v2, v3);
        *(uint32_t*)(smem + SMEM_A + (r0 + mi*16    )*PITCH + cc*2) = *(uint32_t*)&h01;
        *(uint32_t*)(smem + SMEM_A + (r0 + mi*16 + 8)*PITCH + cc*2) = *(uint32_t*)&h23;
      }
    }
  }
  __syncthreads();

  // ---- MMA-2: z[128,64] = a2[128,64] @ W2^T (4 k-steps) ----
  float c2[2][8][4];
  #pragma unroll
  for (int mi = 0; mi < 2; mi++)
    #pragma unroll
    for (int ni = 0; ni < 8; ni++)
      #pragma unroll
      for (int qq = 0; qq < 4; qq++) c2[mi][ni][qq] = 0.f;

  #pragma unroll
  for (int k = 0; k < 4; k++){
    uint32_t bfm[8][2];
    #pragma unroll
    for (int ni = 0; ni < 8; ni++) ldsm_x2(bfm[ni], b_lm + ni*(8*PITCH) + k*32);
    #pragma unroll
    for (int mi = 0; mi < 2; mi++){
      uint32_t af[4];
      ldsm_x4(af, a_lm + mi*(16*PITCH) + k*32);
      #pragma unroll
      for (int ni = 0; ni < 8; ni++) mma16816(c2[mi][ni], af, bfm[ni]);
    }
  }

  // ---- layer 3 in-fragment + quad butterfly + log_softmax ----
  float yp[4][2];
  #pragma unroll
  for (int r = 0; r < 4; r++){ yp[r][0] = 0.f; yp[r][1] = 0.f; }

  {
    const int col = (lane & 3)*2;
    #pragma unroll
    for (int ni = 0; ni < 8; ni++){
      int cc = ni*8 + col;
      float b2a = __ldg(b2 + cc),      b2b = __ldg(b2 + cc + 1);
      float ww00 = __ldg(W3 + cc),      ww01 = __ldg(W3 + cc + 1);
      float ww10 = __ldg(W3 + 64 + cc), ww11 = __ldg(W3 + 64 + cc + 1);
      #pragma unroll
      for (int mi = 0; mi < 2; mi++){
        float z0 = fmaxf(c2[mi][ni][0] + b2a, 0.f);
        float z1 = fmaxf(c2[mi][ni][1] + b2b, 0.f);
        float z2 = fmaxf(c2[mi][ni][2] + b2a, 0.f);
        float z3 = fmaxf(c2[mi][ni][3] + b2b, 0.f);
        yp[mi*2  ][0] += z0*ww00 + z1*ww01;
        yp[mi*2  ][1] += z0*ww10 + z1*ww11;
        yp[mi*2+1][0] += z2*ww00 + z3*ww01;
        yp[mi*2+1][1] += z2*ww10 + z3*ww11;
      }
    }
  }
  #pragma unroll
  for (int m = 1; m <= 2; m <<= 1){
    #pragma unroll
    for (int r = 0; r < 4; r++){
      yp[r][0] += __shfl_xor_sync(0xffffffffu, yp[r][0], m);
      yp[r][1] += __shfl_xor_sync(0xffffffffu, yp[r][1], m);
    }
  }
  if ((lane & 3) == 0){
    float b30 = __ldg(b3), b31 = __ldg(b3 + 1);
    #pragma unroll
    for (int r = 0; r < 4; r++){
      int row = (r >> 1)*16 + (r & 1)*8 + (lane >> 2);
      float y0 = yp[r][0] + b30;
      float y1 = yp[r][1] + b31;
      float mm  = fmaxf(y0, y1);
      float lse = mm + __logf(__expf(y0 - mm) + __expf(y1 - mm));
      ((float2*)out)[blockIdx.x*128 + wid*32 + row] = make_float2(y0 - lse, y1 - lse);
    }
  }
}

extern "C" void kernel_launch(void* const* d_in, const int* in_sizes, int n_in,
                              void* d_out, int out_size)
{
  const float* X   = (const float*)d_in[0];
  const float* Wih = (const float*)d_in[1];
  const float* Whh = (const float*)d_in[2];
  const float* bih = (const float*)d_in[3];
  const float* bhh = (const float*)d_in[4];
  const float* W1  = (const float*)d_in[5];
  const float* b1  = (const float*)d_in[6];
  const float* W2  = (const float*)d_in[7];
  const float* b2  = (const float*)d_in[8];
  const float* W3  = (const float*)d_in[9];
  const float* b3  = (const float*)d_in[10];

  gates_kernel<<<512, 512>>>(X, Wih, bih, bhh);

  cudaFuncSetAttribute(scan_kernel, cudaFuncAttributeMaxDynamicSharedMemorySize, SMEM_TOT);
  scan_kernel<<<NB / 128, 128, SMEM_TOT>>>(Whh, W1, b1, W2, b2, W3, b3, (float*)d_out);
}

// round 17
// speedup vs baseline: 1.3169x; 1.3169x over previous
#include <cuda_runtime.h>
#include <cuda_fp16.h>
#include <cstdint>

#define NB 65536
#define NT 100

// ---- activations: tanh.approx (validated rel_err 8.4e-6) ----
__device__ __forceinline__ float tanhfast(float x){
  float y; asm("tanh.approx.f32 %0, %1;" : "=f"(y) : "f"(x)); return y;
}
__device__ __forceinline__ float sigm(float x){
  return 0.5f + 0.5f*tanhfast(0.5f*x);
}

// per-lane partial dots + 3-shfl butterfly transpose-reduce over the 4-lane group
__device__ __forceinline__ float gate_reduce(float4 x,
    const float4 &w0, const float4 &w1, const float4 &w2, const float4 &w3,
    int dblk, float bsum)
{
  float p0 = x.x*w0.x + x.y*w0.y + x.z*w0.z + x.w*w0.w;
  float p1 = x.x*w1.x + x.y*w1.y + x.z*w1.z + x.w*w1.w;
  float p2 = x.x*w2.x + x.y*w2.y + x.z*w2.z + x.w*w2.w;
  float p3 = x.x*w3.x + x.y*w3.y + x.z*w3.z + x.w*w3.w;
  float s01 = (dblk & 1) ? p0 : p1;
  float r01 = __shfl_xor_sync(0xffffffffu, s01, 1);
  float a   = ((dblk & 1) ? p1 : p0) + r01;
  float s23 = (dblk & 1) ? p2 : p3;
  float r23 = __shfl_xor_sync(0xffffffffu, s23, 1);
  float bb  = ((dblk & 1) ? p3 : p2) + r23;
  float snd = (dblk & 2) ? a : bb;
  float rcv = __shfl_xor_sync(0xffffffffu, snd, 2);
  return ((dblk & 2) ? bb : a) + rcv + bsum;
}

__device__ __forceinline__ void store_gate_h2(unsigned* sp, float gv, int dblk){
  float ghi = __shfl_xor_sync(0xffffffffu, gv, 1);
  if (!(dblk & 1)){
    __half2 hh = __floats2half2_rn(gv, ghi);
    *sp = *(const unsigned*)&hh;
  }
}

// 52 MB fp16 gate scratch: per (t,b) one uint2 = {half2(g0,g1), half2(g2,g3)}
__device__ uint2 g_scratch16[(size_t)NB * NT];

// ============================================================================
// Kernel A: gate precompute -> fp16 scratch (R12-proven, DRAM-bound ~76us).
// PDL trigger at kernel start: lets the scan kernel's gates-independent
// prologue (smem zero + W1 staging + CTA ramp) overlap this kernel's tail.
// ============================================================================
__global__ __launch_bounds__(512)
void gates_kernel(const float* __restrict__ X,   const float* __restrict__ Wih,
                  const float* __restrict__ bih, const float* __restrict__ bhh)
{
#if __CUDA_ARCH__ >= 900
  if (threadIdx.x == 0) cudaTriggerProgrammaticLaunchCompletion();
#endif
  const int lane = threadIdx.x & 31;
  const int wg   = (blockIdx.x * 512 + threadIdx.x) >> 5;
  const int b_i  = lane >> 3;
  const int t_i  = (lane >> 2) & 1;
  const int dblk = lane & 3;

  const float4 w0 = *(const float4*)(Wih +  0 + dblk*4);
  const float4 w1 = *(const float4*)(Wih + 16 + dblk*4);
  const float4 w2 = *(const float4*)(Wih + 32 + dblk*4);
  const float4 w3 = *(const float4*)(Wih + 48 + dblk*4);
  const float bsum = bih[dblk] + bhh[dblk];

  #pragma unroll 1
  for (int rep = 0; rep < 2; rep++){
    const int b = (wg + rep*8192)*4 + b_i;
    const float4* xp = (const float4*)X + ((size_t)b*NT + t_i)*4 + dblk;
    unsigned* sp = (unsigned*)g_scratch16 + ((size_t)t_i*NB + b)*2 + (dblk >> 1);

    #pragma unroll 1
    for (int t0 = 0; t0 < 96; t0 += 8){
      float4 xv[4];
      xv[0] = __ldg(xp);
      xv[1] = __ldg(xp + 8);
      xv[2] = __ldg(xp + 16);
      xv[3] = __ldg(xp + 24);
      xp += 32;
      #pragma unroll
      for (int q = 0; q < 4; q++){
        float gv = gate_reduce(xv[q], w0, w1, w2, w3, dblk, bsum);
        store_gate_h2(sp + (size_t)(2*q)*NB*2, gv, dblk);
      }
      sp += (size_t)8*NB*2;
    }
    {
      float4 xa = __ldg(xp), xb = __ldg(xp + 8);
      float ga = gate_reduce(xa, w0, w1, w2, w3, dblk, bsum);
      float gb = gate_reduce(xb, w0, w1, w2, w3, dblk, bsum);
      store_gate_h2(sp, ga, dblk);
      store_gate_h2(sp + (size_t)2*NB*2, gb, dblk);
    }
  }
}

// ============================================================================
// Kernel B: LSTM scan (triple-buffered prefetch) + HMMA dense layers.
// Launched with programmatic-stream-serialization: prologue (smem zero +
// W1 staging) runs before the grid dependency; gate loads wait on it.
// ============================================================================
#define SMEM_A 0
#define SMEM_B 30720
#define SMEM_TOT 46080
#define PITCH 240

static __device__ __forceinline__ uint32_t smem_u32(const void* p){
  uint32_t a;
  asm("{ .reg .u64 t; cvta.to.shared.u64 t, %1; cvt.u32.u64 %0, t; }" : "=r"(a) : "l"(p));
  return a;
}
__device__ __forceinline__ void ldsm_x4(uint32_t* r, uint32_t addr){
  asm volatile("ldmatrix.sync.aligned.m8n8.x4.shared.b16 {%0,%1,%2,%3}, [%4];"
    : "=r"(r[0]),"=r"(r[1]),"=r"(r[2]),"=r"(r[3]) : "r"(addr));
}
__device__ __forceinline__ void ldsm_x2(uint32_t* r, uint32_t addr){
  asm volatile("ldmatrix.sync.aligned.m8n8.x2.shared.b16 {%0,%1}, [%2];"
    : "=r"(r[0]),"=r"(r[1]) : "r"(addr));
}
__device__ __forceinline__ void mma16816(float* c, const uint32_t* a, const uint32_t* b){
  asm volatile("mma.sync.aligned.m16n8k16.row.col.f32.f16.f16.f32 "
    "{%0,%1,%2,%3}, {%4,%5,%6,%7}, {%8,%9}, {%0,%1,%2,%3};"
    : "+f"(c[0]),"+f"(c[1]),"+f"(c[2]),"+f"(c[3])
    : "r"(a[0]),"r"(a[1]),"r"(a[2]),"r"(a[3]), "r"(b[0]),"r"(b[1]));
}

__device__ __forceinline__ void load_group8(uint2 (&buf)[8], const uint2* gbase, int g){
  const uint2* p = gbase + (size_t)(g*8)*NB;
  #pragma unroll
  for (int i = 0; i < 8; i++) buf[i] = __ldg(p + (size_t)i*NB);
}
__device__ __forceinline__ void load_group4(uint2 (&buf)[8], const uint2* gbase, int g){
  const uint2* p = gbase + (size_t)(g*8)*NB;
  #pragma unroll
  for (int i = 0; i < 4; i++) buf[i] = __ldg(p + (size_t)i*NB);
}

template<int CNT>
__device__ __forceinline__ void consume_group(const uint2 (&buf)[8], float &h, float &c,
    float whh0, float whh1, float whh2, float whh3, float (&hv)[8])
{
  #pragma unroll
  for (int s = 0; s < CNT; s++){
    uint2 u = buf[s];
    float2 glo = __half22float2(*(const __half2*)&u.x);
    float2 ghi = __half22float2(*(const __half2*)&u.y);
    float gi = sigm(glo.x + h*whh0);
    float gf = sigm(glo.y + h*whh1);
    float gg = tanhfast(ghi.x + h*whh2);
    float go = sigm(ghi.y + h*whh3);
    c = gf*c + gi*gg;
    h = go * tanhfast(c);
    hv[s] = fmaxf(h, 0.f);
  }
}

__device__ __forceinline__ void flush_group8(char* arow, int g, const float (&hv)[8]){
  __half2 p0 = __floats2half2_rn(hv[0], hv[1]);
  __half2 p1 = __floats2half2_rn(hv[2], hv[3]);
  __half2 p2 = __floats2half2_rn(hv[4], hv[5]);
  __half2 p3 = __floats2half2_rn(hv[6], hv[7]);
  *(uint4*)(arow + g*16) =
    make_uint4(*(uint32_t*)&p0, *(uint32_t*)&p1, *(uint32_t*)&p2, *(uint32_t*)&p3);
}

__global__ __launch_bounds__(128, 4)
void scan_kernel(const float* __restrict__ Whh, const float* __restrict__ W1,
                 const float* __restrict__ b1,  const float* __restrict__ W2,
                 const float* __restrict__ b2,  const float* __restrict__ W3,
                 const float* __restrict__ b3,  float* __restrict__ out)
{
  extern __shared__ char smem[];
  const int tid  = threadIdx.x;
  const int wid  = tid >> 5;
  const int lane = tid & 31;
  const int b    = blockIdx.x * 128 + tid;
  const uint32_t sbase = smem_u32(smem);

  const uint2* gbase = g_scratch16 + b;

  // ---- gates-independent prologue (overlaps gates_kernel tail via PDL) ----
  // zero A+B regions (provides K zero-padding cols 100..111)
  {
    uint4 z4 = make_uint4(0,0,0,0);
    uint4* zp = (uint4*)smem;
    for (int i = tid; i < SMEM_TOT/16; i += 128) zp[i] = z4;
  }
  __syncthreads();

  // stage W1 -> B as [n=j][k=t] fp16
  {
    __half* sB = (__half*)(smem + SMEM_B);
    for (int i = tid; i < 6400; i += 128){
      int j = i / 100, t = i % 100;
      sB[j*120 + t] = __float2half(W1[i]);
    }
  }

#if __CUDA_ARCH__ >= 900
  cudaGridDependencySynchronize();   // gates scratch fully written + flushed
#endif

  // prologue: issue groups 0,1,2 (24 loads in flight)
  uint2 bf0[8], bf1[8], bf2[8];
  load_group8(bf0, gbase, 0);
  load_group8(bf1, gbase, 1);
  load_group8(bf2, gbase, 2);

  // ---- scan: 12 groups of 8 + tail of 4; distance-16..24 prefetch ----
  const float whh0 = Whh[0], whh1 = Whh[1], whh2 = Whh[2], whh3 = Whh[3];
  char* arow = smem + SMEM_A + tid*PITCH;
  float h = 0.f, c = 0.f;
  float hv[8];

  #pragma unroll 1
  for (int q = 0; q < 4; q++){
    const int g = q*3;
    consume_group<8>(bf0, h, c, whh0, whh1, whh2, whh3, hv);
    if (g + 3 < 12)       load_group8(bf0, gbase, g + 3);
    else if (g + 3 == 12) load_group4(bf0, gbase, 12);
    flush_group8(arow, g, hv);

    consume_group<8>(bf1, h, c, whh0, whh1, whh2, whh3, hv);
    if (g + 4 < 12) load_group8(bf1, gbase, g + 4);
    flush_group8(arow, g + 1, hv);

    consume_group<8>(bf2, h, c, whh0, whh1, whh2, whh3, hv);
    if (g + 5 < 12) load_group8(bf2, gbase, g + 5);
    flush_group8(arow, g + 2, hv);
  }
  // tail: steps 96..99 in bf0 (loaded at g=9)
  consume_group<4>(bf0, h, c, whh0, whh1, whh2, whh3, hv);
  {
    __half2 p0 = __floats2half2_rn(hv[0], hv[1]);
    __half2 p1 = __floats2half2_rn(hv[2], hv[3]);
    *(uint4*)(arow + 192) = make_uint4(*(uint32_t*)&p0, *(uint32_t*)&p1, 0u, 0u);
  }
  __syncthreads();   // all 128 A rows + W1 staged before MMA

  // ldmatrix per-lane base addresses
  const uint32_t a_lm = sbase + SMEM_A
      + (uint32_t)(wid*32 + (lane & 7) + ((lane >> 3) & 1)*8)*PITCH
      + (uint32_t)((lane >> 4) & 1)*16;
  const uint32_t b_lm = sbase + SMEM_B
      + (uint32_t)(lane & 7)*PITCH + (uint32_t)((lane >> 3) & 1)*16;

  // ---- MMA-1: y1[128,64] = hr[128,112] @ W1^T (7 k-steps) ----
  float c1[2][8][4];
  #pragma unroll
  for (int mi = 0; mi < 2; mi++)
    #pragma unroll
    for (int ni = 0; ni < 8; ni++)
      #pragma unroll
      for (int qq = 0; qq < 4; qq++) c1[mi][ni][qq] = 0.f;

  #pragma unroll
  for (int k = 0; k < 7; k++){
    uint32_t bfm[8][2];
    #pragma unroll
    for (int ni = 0; ni < 8; ni++) ldsm_x2(bfm[ni], b_lm + ni*(8*PITCH) + k*32);
    #pragma unroll
    for (int mi = 0; mi < 2; mi++){
      uint32_t af[4];
      ldsm_x4(af, a_lm + mi*(16*PITCH) + k*32);
      #pragma unroll
      for (int ni = 0; ni < 8; ni++) mma16816(c1[mi][ni], af, bfm[ni]);
    }
  }
  __syncthreads();   // everyone done reading A (hr) and B (W1)

  // ---- relu(y1+b1) -> A2 (cols 0..63 of A region); stage W2 -> B ----
  {
    __half* sB = (__half*)(smem + SMEM_B);
    for (int i = tid; i < 4096; i += 128){
      int ko = i >> 6, j = i & 63;
      sB[ko*120 + j] = __float2half(W2[i]);
    }
  }
  {
    const int col = (lane & 3)*2;
    const int r0  = wid*32 + (lane >> 2);
    #pragma unroll
    for (int ni = 0; ni < 8; ni++){
      int cc = ni*8 + col;
      float b1a = __ldg(b1 + cc), b1b = __ldg(b1 + cc + 1);
      #pragma unroll
      for (int mi = 0; mi < 2; mi++){
        float v0 = fmaxf(c1[mi][ni][0] + b1a, 0.f);
        float v1 = fmaxf(c1[mi][ni][1] + b1b, 0.f);
        float v2 = fmaxf(c1[mi][ni][2] + b1a, 0.f);
        float v3 = fmaxf(c1[mi][ni][3] + b1b, 0.f);
        __half2 h01 = __floats2half2_rn(v0, v1);
        __half2 h23 = __floats2half2_rn(v2, v3);
        *(uint32_t*)(smem + SMEM_A + (r0 + mi*16    )*PITCH + cc*2) = *(uint32_t*)&h01;
        *(uint32_t*)(smem + SMEM_A + (r0 + mi*16 + 8)*PITCH + cc*2) = *(uint32_t*)&h23;
      }
    }
  }
  __syncthreads();

  // ---- MMA-2: z[128,64] = a2[128,64] @ W2^T (4 k-steps) ----
  float c2[2][8][4];
  #pragma unroll
  for (int mi = 0; mi < 2; mi++)
    #pragma unroll
    for (int ni = 0; ni < 8; ni++)
      #pragma unroll
      for (int qq = 0; qq < 4; qq++) c2[mi][ni][qq] = 0.f;

  #pragma unroll
  for (int k = 0; k < 4; k++){
    uint32_t bfm[8][2];
    #pragma unroll
    for (int ni = 0; ni < 8; ni++) ldsm_x2(bfm[ni], b_lm + ni*(8*PITCH) + k*32);
    #pragma unroll
    for (int mi = 0; mi < 2; mi++){
      uint32_t af[4];
      ldsm_x4(af, a_lm + mi*(16*PITCH) + k*32);
      #pragma unroll
      for (int ni = 0; ni < 8; ni++) mma16816(c2[mi][ni], af, bfm[ni]);
    }
  }

  // ---- layer 3 in-fragment + quad butterfly + log_softmax ----
  float yp[4][2];
  #pragma unroll
  for (int r = 0; r < 4; r++){ yp[r][0] = 0.f; yp[r][1] = 0.f; }

  {
    const int col = (lane & 3)*2;
    #pragma unroll
    for (int ni = 0; ni < 8; ni++){
      int cc = ni*8 + col;
      float b2a = __ldg(b2 + cc),      b2b = __ldg(b2 + cc + 1);
      float ww00 = __ldg(W3 + cc),      ww01 = __ldg(W3 + cc + 1);
      float ww10 = __ldg(W3 + 64 + cc), ww11 = __ldg(W3 + 64 + cc + 1);
      #pragma unroll
      for (int mi = 0; mi < 2; mi++){
        float z0 = fmaxf(c2[mi][ni][0] + b2a, 0.f);
        float z1 = fmaxf(c2[mi][ni][1] + b2b, 0.f);
        float z2 = fmaxf(c2[mi][ni][2] + b2a, 0.f);
        float z3 = fmaxf(c2[mi][ni][3] + b2b, 0.f);
        yp[mi*2  ][0] += z0*ww00 + z1*ww01;
        yp[mi*2  ][1] += z0*ww10 + z1*ww11;
        yp[mi*2+1][0] += z2*ww00 + z3*ww01;
        yp[mi*2+1][1] += z2*ww10 + z3*ww11;
      }
    }
  }
  #pragma unroll
  for (int m = 1; m <= 2; m <<= 1){
    #pragma unroll
    for (int r = 0; r < 4; r++){
      yp[r][0] += __shfl_xor_sync(0xffffffffu, yp[r][0], m);
      yp[r][1] += __shfl_xor_sync(0xffffffffu, yp[r][1], m);
    }
  }
  if ((lane & 3) == 0){
    float b30 = __ldg(b3), b31 = __ldg(b3 + 1);
    #pragma unroll
    for (int r = 0; r < 4; r++){
      int row = (r >> 1)*16 + (r & 1)*8 + (lane >> 2);
      float y0 = yp[r][0] + b30;
      float y1 = yp[r][1] + b31;
      float mm  = fmaxf(y0, y1);
      float lse = mm + __logf(__expf(y0 - mm) + __expf(y1 - mm));
      ((float2*)out)[blockIdx.x*128 + wid*32 + row] = make_float2(y0 - lse, y1 - lse);
    }
  }
}

extern "C" void kernel_launch(void* const* d_in, const int* in_sizes, int n_in,
                              void* d_out, int out_size)
{
  const float* X   = (const float*)d_in[0];
  const float* Wih = (const float*)d_in[1];
  const float* Whh = (const float*)d_in[2];
  const float* bih = (const float*)d_in[3];
  const float* bhh = (const float*)d_in[4];
  const float* W1  = (const float*)d_in[5];
  const float* b1  = (const float*)d_in[6];
  const float* W2  = (const float*)d_in[7];
  const float* b2  = (const float*)d_in[8];
  const float* W3  = (const float*)d_in[9];
  const float* b3  = (const float*)d_in[10];

  gates_kernel<<<512, 512>>>(X, Wih, bih, bhh);

  cudaFuncSetAttribute(scan_kernel, cudaFuncAttributeMaxDynamicSharedMemorySize, SMEM_TOT);

  // PDL launch of the scan: prologue may start while gates_kernel drains;
  // cudaGridDependencySynchronize() inside guards the scratch reads.
  cudaLaunchConfig_t cfg = {};
  cfg.gridDim  = dim3(NB / 128, 1, 1);
  cfg.blockDim = dim3(128, 1, 1);
  cfg.dynamicSmemBytes = SMEM_TOT;
  cfg.stream = 0;
  cudaLaunchAttribute attr[1];
  attr[0].id = cudaLaunchAttributeProgrammaticStreamSerialization;
  attr[0].val.programmaticStreamSerializationAllowed = 1;
  cfg.attrs = attr;
  cfg.numAttrs = 1;
  cudaLaunchKernelEx(&cfg, scan_kernel, Whh, W1, b1, W2, b2, W3, b3, (float*)d_out);
}